// round 1
// baseline (speedup 1.0000x reference)
#include <cuda_runtime.h>
#include <math.h>
#include <stdint.h>

#define N_NODES 100000
#define N_EDGES 400000
#define FN 64
#define FE 16
#define HIDD 128
#define NH 4
#define DH 32
#define NG 1024
#define FPW 2048
#define NT 5
#define KSEL 32

// ---------------- scratch (device globals; no runtime alloc) ----------------
__device__ float d_XL[N_NODES * HIDD];
__device__ float d_XR[N_NODES * HIDD];
__device__ float d_GO[N_NODES * HIDD];
__device__ float d_H[N_NODES * HIDD];
__device__ float d_P[N_EDGES * NH];
__device__ float d_DEN[N_NODES * NH];
__device__ int   d_cnt[N_NODES];
__device__ int   d_rowptr[N_NODES + 1];
__device__ int   d_cursor[N_NODES];
__device__ int   d_perm[N_EDGES];
__device__ float d_stats[2 * HIDD];
__device__ float d_mv[2 * HIDD];     // mean, inv-std
__device__ float d_emb[NG * HIDD];
__device__ int   d_gstart[NG + 1];

// ---------------- CSR build (counting sort by dst) ----------------
__global__ void k_zero_cnt() {
    int i = blockIdx.x * blockDim.x + threadIdx.x;
    if (i < N_NODES) d_cnt[i] = 0;
}
__global__ void k_count(const int* __restrict__ dst) {
    int e = blockIdx.x * blockDim.x + threadIdx.x;
    if (e < N_EDGES) atomicAdd(&d_cnt[dst[e]], 1);
}
__global__ void k_scan() {  // 1 block, 1024 threads
    __shared__ int ss[1024];
    int t = threadIdx.x;
    const int CH = (N_NODES + 1023) / 1024;  // 98
    int base = t * CH;
    int s = 0;
    for (int i = 0; i < CH; i++) {
        int idx = base + i;
        if (idx < N_NODES) s += d_cnt[idx];
    }
    ss[t] = s;
    __syncthreads();
    for (int off = 1; off < 1024; off <<= 1) {
        int v = 0;
        if (t >= off) v = ss[t - off];
        __syncthreads();
        ss[t] += v;
        __syncthreads();
    }
    int run = (t == 0) ? 0 : ss[t - 1];
    for (int i = 0; i < CH; i++) {
        int idx = base + i;
        if (idx < N_NODES) {
            int c = d_cnt[idx];
            d_rowptr[idx] = run;
            d_cursor[idx] = run;
            run += c;
        }
    }
    if (t == 0) d_rowptr[N_NODES] = N_EDGES;
}
__global__ void k_scatter(const int* __restrict__ dst) {
    int e = blockIdx.x * blockDim.x + threadIdx.x;
    if (e < N_EDGES) {
        int pos = atomicAdd(&d_cursor[dst[e]], 1);
        d_perm[pos] = e;
    }
}

// ---------------- graph segment boundaries (batch is sorted) ----------------
__global__ void k_gstart(const int* __restrict__ batch) {
    int g = blockIdx.x * blockDim.x + threadIdx.x;
    if (g <= NG) {
        int lo = 0, hi = N_NODES;
        while (lo < hi) {
            int mid = (lo + hi) >> 1;
            if (batch[mid] < g) lo = mid + 1; else hi = mid;
        }
        d_gstart[g] = lo;
    }
}

// ---------------- SGEMM: C[N,128] = A[N,K] @ W[K,128] + bias ----------------
#define BM 128
#define BN 128
#define BK 8
__global__ __launch_bounds__(256, 2) void k_gemm(
    const float* __restrict__ Aparam, int asel,
    const float* __restrict__ W, const float* __restrict__ bias,
    int Kdim, int osel)
{
    const float* A = asel ? d_H : Aparam;
    float* C = osel ? d_XR : d_XL;
    __shared__ float As[BK][BM];
    __shared__ float Ws[BK][BN];
    int t = threadIdx.x;
    int tx = t & 15, ty = t >> 4;
    int row0 = blockIdx.x * BM;
    float acc[8][8];
#pragma unroll
    for (int i = 0; i < 8; i++)
#pragma unroll
        for (int j = 0; j < 8; j++) acc[i][j] = 0.f;

    int arow = t >> 1;
    int aseg = (t & 1) * 4;
    int wrow = t >> 5;
    int wcol = (t & 31) * 4;

    for (int k0 = 0; k0 < Kdim; k0 += BK) {
        int gr = row0 + arow;
        float4 av = make_float4(0.f, 0.f, 0.f, 0.f);
        if (gr < N_NODES)
            av = *(const float4*)(A + (size_t)gr * Kdim + k0 + aseg);
        As[aseg + 0][arow] = av.x;
        As[aseg + 1][arow] = av.y;
        As[aseg + 2][arow] = av.z;
        As[aseg + 3][arow] = av.w;
        float4 wv = *(const float4*)(W + (size_t)(k0 + wrow) * HIDD + wcol);
        *(float4*)&Ws[wrow][wcol] = wv;
        __syncthreads();
#pragma unroll
        for (int kk = 0; kk < BK; kk++) {
            float a[8], w[8];
            *(float4*)(a)     = *(float4*)&As[kk][ty * 8];
            *(float4*)(a + 4) = *(float4*)&As[kk][ty * 8 + 4];
            *(float4*)(w)     = *(float4*)&Ws[kk][tx * 8];
            *(float4*)(w + 4) = *(float4*)&Ws[kk][tx * 8 + 4];
#pragma unroll
            for (int i = 0; i < 8; i++)
#pragma unroll
                for (int j = 0; j < 8; j++) acc[i][j] += a[i] * w[j];
        }
        __syncthreads();
    }
#pragma unroll
    for (int i = 0; i < 8; i++) {
        int r = row0 + ty * 8 + i;
        if (r < N_NODES) {
#pragma unroll
            for (int j = 0; j < 8; j++) {
                int c = tx * 8 + j;
                C[(size_t)r * HIDD + c] = acc[i][j] + bias[c];
            }
        }
    }
}

// ---------------- zero helpers ----------------
__global__ void k_zero_den() {
    int i = blockIdx.x * blockDim.x + threadIdx.x;
    if (i < N_NODES * NH) d_DEN[i] = 0.f;
}
__global__ void k_zero_stats() {
    int i = threadIdx.x;
    if (i < 2 * HIDD) d_stats[i] = 0.f;
}

// ---------------- edge pass: scores + exp + denom (warp per edge) ----------------
__global__ __launch_bounds__(256) void k_edge(
    const float* __restrict__ ea, const float* __restrict__ We,
    const float* __restrict__ att,
    const int* __restrict__ srcA, const int* __restrict__ dstA)
{
    __shared__ float sWe[FE * HIDD];
    __shared__ float sAtt[NH * DH];
    int t = threadIdx.x;
    for (int i = t; i < FE * HIDD; i += 256) sWe[i] = We[i];
    if (t < NH * DH) sAtt[t] = att[t];
    __syncthreads();

    int warp = (blockIdx.x * 256 + t) >> 5;
    int lane = t & 31;
    if (warp >= N_EDGES) return;
    int e = warp;
    int s = srcA[e], d = dstA[e];
    const float* ear = ea + (size_t)e * FE;

    float v[4];
#pragma unroll
    for (int j = 0; j < 4; j++) {
        int c = lane + 32 * j;
        float eev = 0.f;
#pragma unroll
        for (int k = 0; k < FE; k++) eev += ear[k] * sWe[k * HIDD + c];
        float x = d_XL[(size_t)s * HIDD + c] + d_XR[(size_t)d * HIDD + c] + eev;
        x = x > 0.f ? x : 0.2f * x;
        v[j] = x * sAtt[c];  // att[h=j][d=lane]
    }
#pragma unroll
    for (int off = 16; off; off >>= 1) {
        v[0] += __shfl_xor_sync(0xffffffffu, v[0], off);
        v[1] += __shfl_xor_sync(0xffffffffu, v[1], off);
        v[2] += __shfl_xor_sync(0xffffffffu, v[2], off);
        v[3] += __shfl_xor_sync(0xffffffffu, v[3], off);
    }
    if (lane < 4) {
        float sc = (lane == 0) ? v[0] : (lane == 1) ? v[1] : (lane == 2) ? v[2] : v[3];
        float p = expf(sc);  // stable: scores are O(1) by construction (no max shift needed)
        d_P[e * NH + lane] = p;
        atomicAdd(&d_DEN[d * NH + lane], p);
    }
}

// ---------------- node pass: alpha-weighted aggregation (warp per dst) ----------------
__global__ __launch_bounds__(256) void k_node(
    const int* __restrict__ srcA, const float* __restrict__ bias)
{
    int warp = (blockIdx.x * blockDim.x + threadIdx.x) >> 5;
    int lane = threadIdx.x & 31;
    if (warp >= N_NODES) return;
    int v = warp;
    float inv[4];
#pragma unroll
    for (int h = 0; h < 4; h++) inv[h] = 1.f / (d_DEN[v * NH + h] + 1e-16f);
    float acc[4] = {0.f, 0.f, 0.f, 0.f};
    int beg = d_rowptr[v], end = d_rowptr[v + 1];
    for (int idx = beg; idx < end; idx++) {
        int e = d_perm[idx];
        int s = srcA[e];
        float al[4];
#pragma unroll
        for (int h = 0; h < 4; h++) al[h] = d_P[e * NH + h] * inv[h];
#pragma unroll
        for (int j = 0; j < 4; j++)
            acc[j] += al[j] * d_XL[(size_t)s * HIDD + lane + 32 * j];
    }
#pragma unroll
    for (int j = 0; j < 4; j++)
        d_GO[(size_t)v * HIDD + lane + 32 * j] = acc[j] + bias[lane + 32 * j];
}

// ---------------- BatchNorm over nodes ----------------
__global__ __launch_bounds__(128) void k_bnstats() {
    int c = threadIdx.x;
    int r0 = blockIdx.x * 512;
    int rend = min(r0 + 512, N_NODES);
    float s = 0.f, s2 = 0.f;
    for (int r = r0; r < rend; r++) {
        float x = d_GO[(size_t)r * HIDD + c];
        s += x; s2 += x * x;
    }
    atomicAdd(&d_stats[c], s);
    atomicAdd(&d_stats[HIDD + c], s2);
}
__global__ void k_bnfin() {
    int c = threadIdx.x;  // 128
    float mu = d_stats[c] / (float)N_NODES;
    float var = d_stats[HIDD + c] / (float)N_NODES - mu * mu;
    d_mv[c] = mu;
    d_mv[HIDD + c] = rsqrtf(var + 1e-5f);
}
__global__ void k_bnapply(const float* __restrict__ gamma,
                          const float* __restrict__ beta, int residual)
{
    int i = blockIdx.x * blockDim.x + threadIdx.x;
    if (i < N_NODES * HIDD) {
        int c = i & (HIDD - 1);
        float x = (d_GO[i] - d_mv[c]) * d_mv[HIDD + c] * gamma[c] + beta[c];
        float y = x > 0.f ? x : expm1f(x);
        d_H[i] = residual ? (y + d_H[i]) : y;
    }
}

// ---------------- graph mean pooling ----------------
__global__ __launch_bounds__(128) void k_pool() {
    int g = blockIdx.x;
    int c = threadIdx.x;
    int beg = d_gstart[g], end = d_gstart[g + 1];
    float s = 0.f;
    for (int r = beg; r < end; r++) s += d_H[(size_t)r * HIDD + c];
    float cnt = (float)(end - beg);
    d_emb[g * HIDD + c] = s / fmaxf(cnt, 1.f);
}

// ---------------- per-task heads ----------------
__global__ __launch_bounds__(128) void k_heads(
    const float* __restrict__ fp, const int* __restrict__ fpidx,
    const float* __restrict__ tw1, const float* __restrict__ tb1,
    const float* __restrict__ tw2, const float* __restrict__ tb2,
    float* __restrict__ out)
{
    int g = blockIdx.x, t = blockIdx.y, j = threadIdx.x;
    __shared__ float fused[HIDD + KSEL];
    __shared__ float red[128];
    fused[j] = d_emb[g * HIDD + j];
    if (j < KSEL)
        fused[HIDD + j] = fp[(size_t)g * FPW + fpidx[t * KSEL + j]];
    __syncthreads();
    const float* w = tw1 + (size_t)t * (HIDD + KSEL) * HIDD;
    float acc = tb1[t * HIDD + j];
    for (int k = 0; k < HIDD + KSEL; k++) acc += fused[k] * w[k * HIDD + j];
    float hm = fmaxf(acc, 0.f);
    red[j] = hm * tw2[t * HIDD + j];
    __syncthreads();
    for (int off = 64; off; off >>= 1) {
        if (j < off) red[j] += red[j + off];
        __syncthreads();
    }
    if (j == 0) out[g * NT + t] = red[0] + tb2[t];
}

// ---------------- driver ----------------
extern "C" void kernel_launch(void* const* d_in, const int* in_sizes, int n_in,
                              void* d_out, int out_size)
{
    const float* x     = (const float*)d_in[0];
    const int*   ei    = (const int*)  d_in[1];
    const float* ea    = (const float*)d_in[2];
    const int*   batch = (const int*)  d_in[3];
    const float* fp    = (const float*)d_in[4];
    const int*   fpidx = (const int*)  d_in[5];
    const float* Wl0   = (const float*)d_in[6];
    const float* bl0   = (const float*)d_in[7];
    const float* Wr0   = (const float*)d_in[8];
    const float* br0   = (const float*)d_in[9];
    const float* We0   = (const float*)d_in[10];
    const float* att0  = (const float*)d_in[11];
    const float* bias0 = (const float*)d_in[12];
    const float* g0    = (const float*)d_in[13];
    const float* b0    = (const float*)d_in[14];
    const float* Wl    = (const float*)d_in[15];
    const float* bl    = (const float*)d_in[16];
    const float* Wr    = (const float*)d_in[17];
    const float* br    = (const float*)d_in[18];
    const float* We    = (const float*)d_in[19];
    const float* att   = (const float*)d_in[20];
    const float* biasc = (const float*)d_in[21];
    const float* gg    = (const float*)d_in[22];
    const float* bb    = (const float*)d_in[23];
    const float* tw1   = (const float*)d_in[24];
    const float* tb1   = (const float*)d_in[25];
    const float* tw2   = (const float*)d_in[26];
    const float* tb2   = (const float*)d_in[27];
    float* out = (float*)d_out;

    const int* srcA = ei;
    const int* dstA = ei + N_EDGES;

    const int GEMM_BLOCKS = (N_NODES + BM - 1) / BM;          // 782
    const int EDGE_BLOCKS = (N_EDGES + 7) / 8;                // warp/edge, 8 warps/block
    const int NODE_BLOCKS = (N_NODES + 7) / 8;
    const int BN_BLOCKS   = (N_NODES + 511) / 512;
    const int EW_BLOCKS   = (N_NODES * HIDD + 255) / 256;

    // CSR by dst + graph starts (recomputed every call; cheap)
    k_zero_cnt<<<(N_NODES + 255) / 256, 256>>>();
    k_count<<<(N_EDGES + 255) / 256, 256>>>(dstA);
    k_scan<<<1, 1024>>>();
    k_scatter<<<(N_EDGES + 255) / 256, 256>>>(dstA);
    k_gstart<<<(NG + 128) / 128, 128>>>(batch);

    // ---- layer 0 (K = 64) ----
    k_gemm<<<GEMM_BLOCKS, 256>>>(x, 0, Wl0, bl0, FN, 0);
    k_gemm<<<GEMM_BLOCKS, 256>>>(x, 0, Wr0, br0, FN, 1);
    k_zero_den<<<(N_NODES * NH + 255) / 256, 256>>>();
    k_edge<<<EDGE_BLOCKS, 256>>>(ea, We0, att0, srcA, dstA);
    k_node<<<NODE_BLOCKS, 256>>>(srcA, bias0);
    k_zero_stats<<<1, 256>>>();
    k_bnstats<<<BN_BLOCKS, 128>>>();
    k_bnfin<<<1, 128>>>();
    k_bnapply<<<EW_BLOCKS, 256>>>(g0, b0, 0);

    // ---- layers 1..3 (K = 128, residual) ----
    for (int i = 0; i < 3; i++) {
        k_gemm<<<GEMM_BLOCKS, 256>>>(nullptr, 1, Wl + (size_t)i * HIDD * HIDD, bl + i * HIDD, HIDD, 0);
        k_gemm<<<GEMM_BLOCKS, 256>>>(nullptr, 1, Wr + (size_t)i * HIDD * HIDD, br + i * HIDD, HIDD, 1);
        k_zero_den<<<(N_NODES * NH + 255) / 256, 256>>>();
        k_edge<<<EDGE_BLOCKS, 256>>>(ea, We + (size_t)i * FE * HIDD, att + i * NH * DH, srcA, dstA);
        k_node<<<NODE_BLOCKS, 256>>>(srcA, biasc + i * HIDD);
        k_zero_stats<<<1, 256>>>();
        k_bnstats<<<BN_BLOCKS, 128>>>();
        k_bnfin<<<1, 128>>>();
        k_bnapply<<<EW_BLOCKS, 256>>>(gg + i * HIDD, bb + i * HIDD, 1);
    }

    // ---- pooling + heads ----
    k_pool<<<NG, 128>>>();
    dim3 hgrid(NG, NT);
    k_heads<<<hgrid, 128>>>(fp, fpidx, tw1, tb1, tw2, tb2, out);
}

// round 2
// speedup vs baseline: 1.1895x; 1.1895x over previous
#include <cuda_runtime.h>
#include <math.h>
#include <stdint.h>

#define N_NODES 100000
#define N_EDGES 400000
#define FN 64
#define FE 16
#define HIDD 128
#define NH 4
#define DH 32
#define NG 1024
#define FPW 2048
#define NT 5
#define KSEL 32

// ---------------- scratch (device globals; no runtime alloc) ----------------
__device__ float d_XL[N_NODES * HIDD];
__device__ float d_XR[N_NODES * HIDD];
__device__ float d_GO[N_NODES * HIDD];
__device__ float d_H[N_NODES * HIDD];
__device__ float d_P[N_EDGES * NH];
__device__ float d_DEN[N_NODES * NH];
__device__ int   d_cnt[N_NODES];
__device__ int   d_rowptr[N_NODES + 1];
__device__ int   d_cursor[N_NODES];
__device__ int2  d_perm[N_EDGES];     // {edge id, src node}
__device__ float d_stats[2 * HIDD];
__device__ float d_mv[2 * HIDD];      // mean, inv-std
__device__ float d_emb[NG * HIDD];
__device__ int   d_gstart[NG + 1];

// ---------------- CSR build (counting sort by dst) ----------------
__global__ void k_zero_cnt() {
    int i = blockIdx.x * blockDim.x + threadIdx.x;
    if (i < N_NODES) d_cnt[i] = 0;
}
__global__ void k_count(const int* __restrict__ dst) {
    int e = blockIdx.x * blockDim.x + threadIdx.x;
    if (e < N_EDGES) atomicAdd(&d_cnt[dst[e]], 1);
}
__global__ void k_scan() {  // 1 block, 1024 threads
    __shared__ int ss[1024];
    int t = threadIdx.x;
    const int CH = (N_NODES + 1023) / 1024;
    int base = t * CH;
    int s = 0;
    for (int i = 0; i < CH; i++) {
        int idx = base + i;
        if (idx < N_NODES) s += d_cnt[idx];
    }
    ss[t] = s;
    __syncthreads();
    for (int off = 1; off < 1024; off <<= 1) {
        int v = 0;
        if (t >= off) v = ss[t - off];
        __syncthreads();
        ss[t] += v;
        __syncthreads();
    }
    int run = (t == 0) ? 0 : ss[t - 1];
    for (int i = 0; i < CH; i++) {
        int idx = base + i;
        if (idx < N_NODES) {
            int c = d_cnt[idx];
            d_rowptr[idx] = run;
            d_cursor[idx] = run;
            run += c;
        }
    }
    if (t == 0) d_rowptr[N_NODES] = N_EDGES;
}
__global__ void k_scatter(const int* __restrict__ src, const int* __restrict__ dst) {
    int e = blockIdx.x * blockDim.x + threadIdx.x;
    if (e < N_EDGES) {
        int pos = atomicAdd(&d_cursor[dst[e]], 1);
        d_perm[pos] = make_int2(e, src[e]);
    }
}

// ---------------- graph segment boundaries (batch is sorted) ----------------
__global__ void k_gstart(const int* __restrict__ batch) {
    int g = blockIdx.x * blockDim.x + threadIdx.x;
    if (g <= NG) {
        int lo = 0, hi = N_NODES;
        while (lo < hi) {
            int mid = (lo + hi) >> 1;
            if (batch[mid] < g) lo = mid + 1; else hi = mid;
        }
        d_gstart[g] = lo;
    }
}

// ---------------- fused dual SGEMM: [XL|XR] = A[N,K] @ [Wl|Wr] + [bl|br] ----
// Weight (K x 256) fully resident in smem; A tile (128 x K) in smem.
// 512 threads, 1 CTA/SM, each thread 8 rows x 8 cols.
__global__ __launch_bounds__(512, 1) void k_dualgemm(
    const float* __restrict__ Aparam, int asel,
    const float* __restrict__ Wlp, const float* __restrict__ Wrp,
    const float* __restrict__ blp, const float* __restrict__ brp,
    int Kdim)
{
    extern __shared__ float sm[];
    float* Ws = sm;                 // [Kdim][256]
    float* As = sm + Kdim * 256;    // [128][Kdim]
    const float* A = asel ? d_H : Aparam;
    int t = threadIdx.x;
    int row0 = blockIdx.x * 128;

    // load weights: Ws[k][0..127] = Wl[k], Ws[k][128..255] = Wr[k]
    int nW4 = Kdim * 128 / 4;
    for (int i = t; i < nW4; i += 512) {
        int k = (i * 4) >> 7, c = (i * 4) & 127;
        float4 v = ((const float4*)Wlp)[i];
        *(float4*)&Ws[k * 256 + c] = v;
        float4 v2 = ((const float4*)Wrp)[i];
        *(float4*)&Ws[k * 256 + 128 + c] = v2;
    }
    // load A tile (row-major, coalesced)
    int nA4 = 128 * Kdim / 4;
    for (int i = t; i < nA4; i += 512) {
        int r = (i * 4) / Kdim;
        int k = (i * 4) % Kdim;
        int gr = row0 + r;
        float4 v = make_float4(0.f, 0.f, 0.f, 0.f);
        if (gr < N_NODES) v = *(const float4*)(A + (size_t)gr * Kdim + k);
        *(float4*)&As[r * Kdim + k] = v;
    }
    __syncthreads();

    int tx = t & 31;   // col group: 8 cols of 256
    int ty = t >> 5;   // row group: 8 rows of 128
    float acc[8][8];
#pragma unroll
    for (int i = 0; i < 8; i++)
#pragma unroll
        for (int j = 0; j < 8; j++) acc[i][j] = 0.f;

#pragma unroll 4
    for (int k = 0; k < Kdim; k++) {
        float w[8];
        *(float4*)(w)     = *(float4*)&Ws[k * 256 + tx * 8];
        *(float4*)(w + 4) = *(float4*)&Ws[k * 256 + tx * 8 + 4];
        float a[8];
#pragma unroll
        for (int i = 0; i < 8; i++) a[i] = As[(ty * 8 + i) * Kdim + k];
#pragma unroll
        for (int i = 0; i < 8; i++)
#pragma unroll
            for (int j = 0; j < 8; j++) acc[i][j] += a[i] * w[j];
    }

    // epilogue: tx<16 -> XL (cols tx*8), tx>=16 -> XR
    float* C = (tx < 16) ? d_XL : d_XR;
    const float* bp = (tx < 16) ? blp : brp;
    int cc = (tx & 15) * 8;
    float bsel[8];
#pragma unroll
    for (int j = 0; j < 8; j++) bsel[j] = bp[cc + j];
#pragma unroll
    for (int i = 0; i < 8; i++) {
        int r = row0 + ty * 8 + i;
        if (r < N_NODES) {
            float4 o0 = make_float4(acc[i][0] + bsel[0], acc[i][1] + bsel[1],
                                    acc[i][2] + bsel[2], acc[i][3] + bsel[3]);
            float4 o1 = make_float4(acc[i][4] + bsel[4], acc[i][5] + bsel[5],
                                    acc[i][6] + bsel[6], acc[i][7] + bsel[7]);
            *(float4*)(C + (size_t)r * HIDD + cc)     = o0;
            *(float4*)(C + (size_t)r * HIDD + cc + 4) = o1;
        }
    }
}

// ---------------- zero helpers ----------------
__global__ void k_zero_den() {
    int i = blockIdx.x * blockDim.x + threadIdx.x;
    if (i < N_NODES * NH) d_DEN[i] = 0.f;
}
__global__ void k_zero_stats() {
    int i = threadIdx.x;
    if (i < 2 * HIDD) d_stats[i] = 0.f;
}

// ---------------- edge pass: scores + exp + denom (warp per edge) ----------------
__global__ __launch_bounds__(256) void k_edge(
    const float* __restrict__ ea, const float* __restrict__ We,
    const float* __restrict__ att,
    const int* __restrict__ srcA, const int* __restrict__ dstA)
{
    __shared__ float sWe[FE * HIDD];
    __shared__ float sAtt[NH * DH];
    int t = threadIdx.x;
    for (int i = t; i < FE * HIDD; i += 256) sWe[i] = We[i];
    if (t < NH * DH) sAtt[t] = att[t];
    __syncthreads();

    int warp = (blockIdx.x * 256 + t) >> 5;
    int lane = t & 31;
    if (warp >= N_EDGES) return;
    int e = warp;
    int s = srcA[e], d = dstA[e];

    // edge attr: 16 floats, broadcast across the warp via L1
    float ear[16];
    {
        const float4* p = (const float4*)(ea + (size_t)e * FE);
        float4 a0 = p[0], a1 = p[1], a2 = p[2], a3 = p[3];
        ear[0] = a0.x; ear[1] = a0.y; ear[2] = a0.z; ear[3] = a0.w;
        ear[4] = a1.x; ear[5] = a1.y; ear[6] = a1.z; ear[7] = a1.w;
        ear[8] = a2.x; ear[9] = a2.y; ear[10] = a2.z; ear[11] = a2.w;
        ear[12] = a3.x; ear[13] = a3.y; ear[14] = a3.z; ear[15] = a3.w;
    }
    int c0 = lane * 4;
    float4 xl = *(const float4*)(d_XL + (size_t)s * HIDD + c0);
    float4 xr = *(const float4*)(d_XR + (size_t)d * HIDD + c0);
    float e0 = 0.f, e1 = 0.f, e2 = 0.f, e3 = 0.f;
#pragma unroll
    for (int k = 0; k < FE; k++) {
        float4 wv = *(const float4*)&sWe[k * HIDD + c0];
        float ak = ear[k];
        e0 += ak * wv.x; e1 += ak * wv.y; e2 += ak * wv.z; e3 += ak * wv.w;
    }
    float x0 = xl.x + xr.x + e0; x0 = x0 > 0.f ? x0 : 0.2f * x0;
    float x1 = xl.y + xr.y + e1; x1 = x1 > 0.f ? x1 : 0.2f * x1;
    float x2 = xl.z + xr.z + e2; x2 = x2 > 0.f ? x2 : 0.2f * x2;
    float x3 = xl.w + xr.w + e3; x3 = x3 > 0.f ? x3 : 0.2f * x3;
    float sc = x0 * sAtt[c0] + x1 * sAtt[c0 + 1] + x2 * sAtt[c0 + 2] + x3 * sAtt[c0 + 3];
    // reduce within each 8-lane group (one head per group)
    sc += __shfl_xor_sync(0xffffffffu, sc, 1);
    sc += __shfl_xor_sync(0xffffffffu, sc, 2);
    sc += __shfl_xor_sync(0xffffffffu, sc, 4);
    if ((lane & 7) == 0) {
        int h = lane >> 3;
        float p = expf(sc);  // scores are O(1) by construction; no max-shift needed
        d_P[e * NH + h] = p;
        atomicAdd(&d_DEN[d * NH + h], p);
    }
}

// ---------------- node pass: alpha-weighted aggregation (warp per dst) ----------------
__global__ __launch_bounds__(256) void k_node(const float* __restrict__ bias)
{
    int warp = (blockIdx.x * blockDim.x + threadIdx.x) >> 5;
    int lane = threadIdx.x & 31;
    if (warp >= N_NODES) return;
    int v = warp;
    int h = lane >> 3;
    float inv = 1.f / (d_DEN[v * NH + h] + 1e-16f);
    float4 acc = make_float4(0.f, 0.f, 0.f, 0.f);
    int beg = d_rowptr[v], end = d_rowptr[v + 1];
    for (int idx = beg; idx < end; idx++) {
        int2 es = d_perm[idx];
        float al = d_P[es.x * NH + h] * inv;
        float4 xv = *(const float4*)(d_XL + (size_t)es.y * HIDD + lane * 4);
        acc.x += al * xv.x; acc.y += al * xv.y;
        acc.z += al * xv.z; acc.w += al * xv.w;
    }
    float4 bv = *(const float4*)(bias + lane * 4);
    acc.x += bv.x; acc.y += bv.y; acc.z += bv.z; acc.w += bv.w;
    *(float4*)(d_GO + (size_t)v * HIDD + lane * 4) = acc;
}

// ---------------- BatchNorm over nodes ----------------
__global__ __launch_bounds__(128) void k_bnstats() {
    int c = threadIdx.x;
    int r0 = blockIdx.x * 512;
    int rend = min(r0 + 512, N_NODES);
    float s = 0.f, s2 = 0.f;
    for (int r = r0; r < rend; r++) {
        float x = d_GO[(size_t)r * HIDD + c];
        s += x; s2 += x * x;
    }
    atomicAdd(&d_stats[c], s);
    atomicAdd(&d_stats[HIDD + c], s2);
}
__global__ void k_bnfin() {
    int c = threadIdx.x;
    float mu = d_stats[c] / (float)N_NODES;
    float var = d_stats[HIDD + c] / (float)N_NODES - mu * mu;
    d_mv[c] = mu;
    d_mv[HIDD + c] = rsqrtf(var + 1e-5f);
}
__global__ void k_bnapply(const float* __restrict__ gamma,
                          const float* __restrict__ beta, int residual)
{
    int i = blockIdx.x * blockDim.x + threadIdx.x;
    if (i < N_NODES * HIDD) {
        int c = i & (HIDD - 1);
        float x = (d_GO[i] - d_mv[c]) * d_mv[HIDD + c] * gamma[c] + beta[c];
        float y = x > 0.f ? x : expm1f(x);
        d_H[i] = residual ? (y + d_H[i]) : y;
    }
}

// ---------------- graph mean pooling ----------------
__global__ __launch_bounds__(128) void k_pool() {
    int g = blockIdx.x;
    int c = threadIdx.x;
    int beg = d_gstart[g], end = d_gstart[g + 1];
    float s = 0.f;
    for (int r = beg; r < end; r++) s += d_H[(size_t)r * HIDD + c];
    float cnt = (float)(end - beg);
    d_emb[g * HIDD + c] = s / fmaxf(cnt, 1.f);
}

// ---------------- per-task heads ----------------
__global__ __launch_bounds__(128) void k_heads(
    const float* __restrict__ fp, const int* __restrict__ fpidx,
    const float* __restrict__ tw1, const float* __restrict__ tb1,
    const float* __restrict__ tw2, const float* __restrict__ tb2,
    float* __restrict__ out)
{
    int g = blockIdx.x, t = blockIdx.y, j = threadIdx.x;
    __shared__ float fused[HIDD + KSEL];
    __shared__ float red[128];
    fused[j] = d_emb[g * HIDD + j];
    if (j < KSEL)
        fused[HIDD + j] = fp[(size_t)g * FPW + fpidx[t * KSEL + j]];
    __syncthreads();
    const float* w = tw1 + (size_t)t * (HIDD + KSEL) * HIDD;
    float acc = tb1[t * HIDD + j];
    for (int k = 0; k < HIDD + KSEL; k++) acc += fused[k] * w[k * HIDD + j];
    float hm = fmaxf(acc, 0.f);
    red[j] = hm * tw2[t * HIDD + j];
    __syncthreads();
    for (int off = 64; off; off >>= 1) {
        if (j < off) red[j] += red[j + off];
        __syncthreads();
    }
    if (j == 0) out[g * NT + t] = red[0] + tb2[t];
}

// ---------------- driver ----------------
extern "C" void kernel_launch(void* const* d_in, const int* in_sizes, int n_in,
                              void* d_out, int out_size)
{
    const float* x     = (const float*)d_in[0];
    const int*   ei    = (const int*)  d_in[1];
    const float* ea    = (const float*)d_in[2];
    const int*   batch = (const int*)  d_in[3];
    const float* fp    = (const float*)d_in[4];
    const int*   fpidx = (const int*)  d_in[5];
    const float* Wl0   = (const float*)d_in[6];
    const float* bl0   = (const float*)d_in[7];
    const float* Wr0   = (const float*)d_in[8];
    const float* br0   = (const float*)d_in[9];
    const float* We0   = (const float*)d_in[10];
    const float* att0  = (const float*)d_in[11];
    const float* bias0 = (const float*)d_in[12];
    const float* g0    = (const float*)d_in[13];
    const float* b0    = (const float*)d_in[14];
    const float* Wl    = (const float*)d_in[15];
    const float* bl    = (const float*)d_in[16];
    const float* Wr    = (const float*)d_in[17];
    const float* br    = (const float*)d_in[18];
    const float* We    = (const float*)d_in[19];
    const float* att   = (const float*)d_in[20];
    const float* biasc = (const float*)d_in[21];
    const float* gg    = (const float*)d_in[22];
    const float* bb    = (const float*)d_in[23];
    const float* tw1   = (const float*)d_in[24];
    const float* tb1   = (const float*)d_in[25];
    const float* tw2   = (const float*)d_in[26];
    const float* tb2   = (const float*)d_in[27];
    float* out = (float*)d_out;

    const int* srcA = ei;
    const int* dstA = ei + N_EDGES;

    // allow 192KB dynamic smem for the dual-GEMM (idempotent; not a stream op)
    static int smem_set = 0;
    if (!smem_set) {
        cudaFuncSetAttribute(k_dualgemm, cudaFuncAttributeMaxDynamicSharedMemorySize,
                             200 * 1024);
        smem_set = 1;
    }

    const int GEMM_BLOCKS = (N_NODES + 127) / 128;           // 782
    const int EDGE_BLOCKS = (N_EDGES + 7) / 8;               // warp/edge
    const int NODE_BLOCKS = (N_NODES + 7) / 8;
    const int BN_BLOCKS   = (N_NODES + 511) / 512;
    const int EW_BLOCKS   = (N_NODES * HIDD + 255) / 256;

    // CSR build interleaved so the dual-GEMM lands early for profiling
    k_zero_cnt<<<(N_NODES + 255) / 256, 256>>>();
    k_count<<<(N_EDGES + 255) / 256, 256>>>(dstA);
    k_scan<<<1, 1024>>>();

    // ---- layer 0 (K = 64) ----
    k_dualgemm<<<GEMM_BLOCKS, 512, FN * 256 * 4 + 128 * FN * 4>>>(
        x, 0, Wl0, Wr0, bl0, br0, FN);
    k_scatter<<<(N_EDGES + 255) / 256, 256>>>(srcA, dstA);
    k_gstart<<<(NG + 128) / 128, 128>>>(batch);
    k_zero_den<<<(N_NODES * NH + 255) / 256, 256>>>();
    k_edge<<<EDGE_BLOCKS, 256>>>(ea, We0, att0, srcA, dstA);
    k_node<<<NODE_BLOCKS, 256>>>(bias0);
    k_zero_stats<<<1, 256>>>();
    k_bnstats<<<BN_BLOCKS, 128>>>();
    k_bnfin<<<1, 128>>>();
    k_bnapply<<<EW_BLOCKS, 256>>>(g0, b0, 0);

    // ---- layers 1..3 (K = 128, residual) ----
    for (int i = 0; i < 3; i++) {
        k_dualgemm<<<GEMM_BLOCKS, 512, HIDD * 256 * 4 + 128 * HIDD * 4>>>(
            nullptr, 1,
            Wl + (size_t)i * HIDD * HIDD, Wr + (size_t)i * HIDD * HIDD,
            bl + i * HIDD, br + i * HIDD, HIDD);
        k_zero_den<<<(N_NODES * NH + 255) / 256, 256>>>();
        k_edge<<<EDGE_BLOCKS, 256>>>(ea, We + (size_t)i * FE * HIDD, att + i * NH * DH,
                                     srcA, dstA);
        k_node<<<NODE_BLOCKS, 256>>>(biasc + i * HIDD);
        k_zero_stats<<<1, 256>>>();
        k_bnstats<<<BN_BLOCKS, 128>>>();
        k_bnfin<<<1, 128>>>();
        k_bnapply<<<EW_BLOCKS, 256>>>(gg + i * HIDD, bb + i * HIDD, 1);
    }

    // ---- pooling + heads ----
    k_pool<<<NG, 128>>>();
    dim3 hgrid(NG, NT);
    k_heads<<<hgrid, 128>>>(fp, fpidx, tw1, tb1, tw2, tb2, out);
}